// round 3
// baseline (speedup 1.0000x reference)
#include <cuda_runtime.h>
#include <cuda.h>
#include <cuda_bf16.h>
#include <cstdint>

// ---------------------------------------------------------------------------
// Problem constants
// ---------------------------------------------------------------------------
#define NROWS   100000
#define INCH    512
#define OUTCH   512
#define KTOT    3072            // 6 segments * 512
#define NCOLS   1024            // out_re (512) ++ out_im (512)

#define TM      128             // CTA tile M
#define TN      128             // CTA tile N
#define KB      64              // bf16 elems per K-block (128 bytes = SW128 row)
#define STAGES  4
#define NITERS  48              // 6 segs * (512/64)

#define M_TILES 782             // ceil(100000/128)
#define N_TILES 8               // 1024/128

// SMEM layout (relative to 1024-aligned base)
#define OFF_FULL   0            // 4 full mbarriers (8B each)
#define OFF_STAGE0 1024
#define A_BYTES    (TM * KB * 2)          // 16384
#define B_BYTES    (TN * KB * 2)          // 16384
#define STAGE_BYTES (A_BYTES + B_BYTES)   // 32768
#define SMEM_DYN   (1024 /*align slack*/ + 1024 + STAGES * STAGE_BYTES)  // 133120

// ---------------------------------------------------------------------------
// Device scratch (allocation-free rule: __device__ globals)
// ---------------------------------------------------------------------------
// A planes: 0 = re_hi, 1 = re_lo, 2 = im_hi, 3 = im_lo ; each [NROWS][INCH] bf16
__device__ __nv_bfloat16 g_A[4ull * NROWS * INCH];
// B: [NCOLS][KTOT] bf16, K-major
__device__ __nv_bfloat16 g_B[(size_t)NCOLS * KTOT];

// ---------------------------------------------------------------------------
// PTX helpers (generic-PTX only: no tcgen05 / TMEM / cta_group)
// ---------------------------------------------------------------------------
__device__ __forceinline__ uint32_t smem_u32(const void* p) {
    uint32_t a;
    asm("{ .reg .u64 t; cvta.to.shared.u64 t, %1; cvt.u32.u64 %0, t; }" : "=r"(a) : "l"(p));
    return a;
}
#define MBARRIER_INIT(addr, cnt) \
    asm volatile("mbarrier.init.shared.b64 [%0], %1;" :: "r"((uint32_t)(addr)), "r"((uint32_t)(cnt)) : "memory")
#define MBARRIER_EXPECT_TX(addr, bytes) \
    asm volatile("mbarrier.arrive.expect_tx.shared.b64 _, [%0], %1;" :: "r"((uint32_t)(addr)), "r"((uint32_t)(bytes)) : "memory")
#define FENCE_PROXY_ASYNC_SHARED_CTA() \
    asm volatile("fence.proxy.async.shared::cta;" ::: "memory")

#define MBARRIER_WAIT_PARITY(mbar_smem_addr, phase_parity) do { \
    uint32_t _mbar = (uint32_t)(mbar_smem_addr); \
    uint32_t _parity = (uint32_t)(phase_parity); \
    uint32_t _done; \
    asm volatile("{\n\t.reg .pred p;\n\t" \
        "mbarrier.try_wait.parity.acquire.cta.shared::cta.b64 p, [%1], %2;\n\t" \
        "selp.b32 %0, 1, 0, p;\n\t}" : "=r"(_done) : "r"(_mbar), "r"(_parity) : "memory"); \
    if (!_done) { \
        asm volatile("{\n\t.reg .pred P1;\n\t" \
            "WAIT_LOOP_%=:\n\t" \
            "mbarrier.try_wait.parity.acquire.cta.shared::cta.b64 P1, [%0], %1, 0x989680;\n\t" \
            "@P1 bra.uni WAIT_DONE_%=;\n\t" \
            "bra.uni WAIT_LOOP_%=;\n\t" \
            "WAIT_DONE_%=:\n\t}" :: "r"(_mbar), "r"(_parity) : "memory"); \
    } \
} while(0)

#define TMA_LOAD_3D(smem_addr, tmap, cx, cy, cz, mbar) \
    asm volatile("cp.async.bulk.tensor.3d.shared::cta.global.tile.mbarrier::complete_tx::bytes " \
        "[%0], [%1, {%2, %3, %4}], [%5];" \
        :: "r"((uint32_t)(smem_addr)), "l"(tmap), "r"((int32_t)(cx)), "r"((int32_t)(cy)), "r"((int32_t)(cz)), \
           "r"((uint32_t)(mbar)) : "memory")

#define LDSM_X4(r0, r1, r2, r3, addr) \
    asm volatile("ldmatrix.sync.aligned.m8n8.x4.shared.b16 {%0,%1,%2,%3}, [%4];" \
        : "=r"(r0), "=r"(r1), "=r"(r2), "=r"(r3) : "r"(addr))

#define MMA_16816(c0, c1, c2, c3, a0, a1, a2, a3, b0, b1) \
    asm volatile("mma.sync.aligned.m16n8k16.row.col.f32.bf16.bf16.f32 " \
        "{%0,%1,%2,%3}, {%4,%5,%6,%7}, {%8,%9}, {%0,%1,%2,%3};" \
        : "+f"(c0), "+f"(c1), "+f"(c2), "+f"(c3) \
        : "r"(a0), "r"(a1), "r"(a2), "r"(a3), "r"(b0), "r"(b1))

// ---------------------------------------------------------------------------
// Prep kernels
// ---------------------------------------------------------------------------
__global__ void prep_A_kernel(const float* __restrict__ xre, const float* __restrict__ xim) {
    size_t i = (size_t)blockIdx.x * blockDim.x + threadIdx.x;
    const size_t P = (size_t)NROWS * INCH;
    if (i >= P) return;
    float vr = xre[i], vi = xim[i];
    __nv_bfloat16 hr = __float2bfloat16(vr);
    __nv_bfloat16 lr = __float2bfloat16(vr - __bfloat162float(hr));
    __nv_bfloat16 hi = __float2bfloat16(vi);
    __nv_bfloat16 li = __float2bfloat16(vi - __bfloat162float(hi));
    g_A[0 * P + i] = hr;
    g_A[1 * P + i] = lr;
    g_A[2 * P + i] = hi;
    g_A[3 * P + i] = li;
}

// Build B[1024][3072]:
//   A plane order per segment:  [re_hi, re_lo, re_hi, im_hi, im_lo, im_hi]
//   B segment content:          [W_hi,  W_hi,  W_lo,  V_hi,  V_hi,  V_lo]
//   o <  512 (out_re): W = Re,  V = -Im
//   o >= 512 (out_im): W = Im,  V =  Re
__global__ void prep_B_kernel(const float* __restrict__ Re, const float* __restrict__ Im) {
    int idx = blockIdx.x * blockDim.x + threadIdx.x;
    if (idx >= NCOLS * KTOT) return;
    int o   = idx / KTOT;
    int k   = idx % KTOT;
    int seg = k / 512;
    int ii  = k % 512;
    float w;
    if (o < 512) w = (seg < 3) ? Re[o * 512 + ii] : -Im[o * 512 + ii];
    else         w = (seg < 3) ? Im[(o - 512) * 512 + ii] : Re[(o - 512) * 512 + ii];
    __nv_bfloat16 h = __float2bfloat16(w);
    __nv_bfloat16 v = h;
    if (seg == 2 || seg == 5) v = __float2bfloat16(w - __bfloat162float(h));
    g_B[idx] = v;
}

// ---------------------------------------------------------------------------
// GEMM kernel: D[m][n] = sum_k A[m][k] * B[n][k]
// CTA tile 128x128, 8 warps (4 along M x 2 along N), warp tile 32x64.
// TMA 4-stage pipeline -> ldmatrix -> mma.sync m16n8k16 bf16, fp32 acc.
// ---------------------------------------------------------------------------
__global__ void __launch_bounds__(256, 1) gemm_kernel(
    float* __restrict__ out,
    const __grid_constant__ CUtensorMap tmA,
    const __grid_constant__ CUtensorMap tmB)
{
    extern __shared__ char smem_raw[];
    const uint32_t base = (smem_u32(smem_raw) + 1023u) & ~1023u;
    const int tid  = threadIdx.x;
    const int wid  = tid >> 5;
    const int lane = tid & 31;
    const int n_tile = blockIdx.x;   // 0..7 (fastest -> A-tile reuse in L2)
    const int m_tile = blockIdx.y;   // 0..781

    const int warp_m = (wid & 3) * 32;   // 0,32,64,96
    const int warp_n = (wid >> 2) * 64;  // 0,64

    if (tid == 0) {
        #pragma unroll
        for (int s = 0; s < STAGES; ++s) MBARRIER_INIT(base + OFF_FULL + s * 8, 1);
        FENCE_PROXY_ASYNC_SHARED_CTA();
    }
    __syncthreads();

    // Prologue: fill all stages (seg==0 for j<8).
    if (tid == 0) {
        #pragma unroll
        for (int j = 0; j < STAGES; ++j) {
            uint32_t full = base + OFF_FULL + j * 8;
            MBARRIER_EXPECT_TX(full, STAGE_BYTES);
            uint32_t a_dst = base + OFF_STAGE0 + j * STAGE_BYTES;
            TMA_LOAD_3D(a_dst, &tmA, j * KB, m_tile * TM, 0, full);
            TMA_LOAD_3D(a_dst + A_BYTES, &tmB, j * KB, n_tile * TN, 0, full);
        }
    }

    // Per-lane row bases and SW128 XOR masks (mask = (row%8)<<4, bits [6:4]).
    // k-chunk byte offset (khalf*16 + ks*32) also lives in bits [6:4], so
    // (koff ^ mask) is carry-free and must be XORed, not added.
    // A: row = warp_m + (lane&15), khalf = lane>>4
    const uint32_t a_row   = (uint32_t)(warp_m + (lane & 15));
    const uint32_t a_rowba = base + OFF_STAGE0 + a_row * 128u;
    const uint32_t a_mask  = (a_row & 7u) << 4;
    const uint32_t a_kh    = (uint32_t)(lane >> 4) * 16u;
    // B: row = warp_n + (lane&7) + (lane>>4)*8, khalf = (lane>>3)&1
    const uint32_t b_row   = (uint32_t)(warp_n + (lane & 7) + ((lane >> 4) << 3));
    const uint32_t b_rowba = base + OFF_STAGE0 + A_BYTES + b_row * 128u;
    const uint32_t b_mask  = (b_row & 7u) << 4;
    const uint32_t b_kh    = (uint32_t)((lane >> 3) & 1) * 16u;

    float acc[2][8][4];
    #pragma unroll
    for (int mi = 0; mi < 2; ++mi)
        #pragma unroll
        for (int ni = 0; ni < 8; ++ni)
            #pragma unroll
            for (int r = 0; r < 4; ++r) acc[mi][ni][r] = 0.0f;

    for (int it = 0; it < NITERS; ++it) {
        const int s  = it & (STAGES - 1);
        const int ph = (it >> 2) & 1;
        MBARRIER_WAIT_PARITY(base + OFF_FULL + s * 8, ph);

        const uint32_t a_st = a_rowba + s * STAGE_BYTES;
        const uint32_t b_st = b_rowba + s * STAGE_BYTES;

        #pragma unroll
        for (int ks = 0; ks < 4; ++ks) {
            const uint32_t a_ko = (a_kh + (uint32_t)ks * 32u) ^ a_mask;
            const uint32_t b_ko = (b_kh + (uint32_t)ks * 32u) ^ b_mask;
            uint32_t a[2][4];
            #pragma unroll
            for (int mi = 0; mi < 2; ++mi)
                LDSM_X4(a[mi][0], a[mi][1], a[mi][2], a[mi][3],
                        a_st + mi * 2048 + a_ko);
            uint32_t b[4][4];
            #pragma unroll
            for (int ni2 = 0; ni2 < 4; ++ni2)
                LDSM_X4(b[ni2][0], b[ni2][1], b[ni2][2], b[ni2][3],
                        b_st + ni2 * 2048 + b_ko);
            #pragma unroll
            for (int mi = 0; mi < 2; ++mi)
                #pragma unroll
                for (int ni = 0; ni < 8; ++ni) {
                    const int ni2 = ni >> 1;
                    const int h   = (ni & 1) * 2;   // 0 -> regs {0,1}, 1 -> {2,3}
                    MMA_16816(acc[mi][ni][0], acc[mi][ni][1], acc[mi][ni][2], acc[mi][ni][3],
                              a[mi][0], a[mi][1], a[mi][2], a[mi][3],
                              b[ni2][h], b[ni2][h + 1]);
                }
        }

        __syncthreads();   // all warps done reading stage s
        if (tid == 0 && it + STAGES < NITERS) {
            const int j = it + STAGES;
            const int seg = j >> 3, kb = j & 7;
            const int plane = (seg < 3) ? ((seg == 1) ? 1 : 0) : ((seg == 4) ? 3 : 2);
            uint32_t full = base + OFF_FULL + s * 8;
            MBARRIER_EXPECT_TX(full, STAGE_BYTES);
            uint32_t a_dst = base + OFF_STAGE0 + s * STAGE_BYTES;
            TMA_LOAD_3D(a_dst, &tmA, kb * KB, m_tile * TM, plane, full);
            TMA_LOAD_3D(a_dst + A_BYTES, &tmB, seg * 512 + kb * KB, n_tile * TN, 0, full);
        }
    }

    // ---- Epilogue: fragments -> GMEM ----
    // D frag m16n8: {c0,c1} at row lane/4, cols 2*(lane%4)+{0,1}; {c2,c3} at row+8.
    const int m_base = m_tile * TM + warp_m;
    const int n_base = n_tile * TN + warp_n;
    #pragma unroll
    for (int mi = 0; mi < 2; ++mi) {
        #pragma unroll
        for (int ni = 0; ni < 8; ++ni) {
            int r0 = m_base + mi * 16 + (lane >> 2);
            int c  = n_base + ni * 8 + (lane & 3) * 2;
            int plane = c >> 9;
            int col   = c & 511;
            float* p = out + (size_t)plane * ((size_t)NROWS * OUTCH) + (size_t)r0 * OUTCH + col;
            if (r0 < NROWS)
                *reinterpret_cast<float2*>(p) = make_float2(acc[mi][ni][0], acc[mi][ni][1]);
            if (r0 + 8 < NROWS)
                *reinterpret_cast<float2*>(p + 8 * OUTCH) = make_float2(acc[mi][ni][2], acc[mi][ni][3]);
        }
    }
}

// ---------------------------------------------------------------------------
// Host launch
// ---------------------------------------------------------------------------
typedef CUresult (*EncodeTiledFn)(
    CUtensorMap*, CUtensorMapDataType, cuuint32_t, void*,
    const cuuint64_t*, const cuuint64_t*, const cuuint32_t*, const cuuint32_t*,
    CUtensorMapInterleave, CUtensorMapSwizzle, CUtensorMapL2promotion, CUtensorMapFloatOOBfill);

extern "C" void kernel_launch(void* const* d_in, const int* in_sizes, int n_in,
                              void* d_out, int out_size) {
    const float* x_re = (const float*)d_in[0];
    const float* x_im = (const float*)d_in[1];
    const float* Re   = (const float*)d_in[2];
    const float* Im   = (const float*)d_in[3];
    float* out = (float*)d_out;

    void *pA = nullptr, *pB = nullptr;
    cudaGetSymbolAddress(&pA, g_A);
    cudaGetSymbolAddress(&pB, g_B);

    const size_t P = (size_t)NROWS * INCH;
    prep_A_kernel<<<(unsigned)((P + 255) / 256), 256>>>(x_re, x_im);
    prep_B_kernel<<<(NCOLS * KTOT + 255) / 256, 256>>>(Re, Im);

    EncodeTiledFn encode = nullptr;
    cudaDriverEntryPointQueryResult qr;
    cudaGetDriverEntryPointByVersion("cuTensorMapEncodeTiled", (void**)&encode,
                                     12000, cudaEnableDefault, &qr);
    if (!encode) return;

    CUtensorMap tmA{}, tmB{};
    {
        cuuint64_t dims[3] = {INCH, NROWS, 4};
        cuuint64_t str[2]  = {INCH * 2ull, (cuuint64_t)NROWS * INCH * 2ull};
        cuuint32_t box[3]  = {KB, TM, 1};
        cuuint32_t es[3]   = {1, 1, 1};
        encode(&tmA, CU_TENSOR_MAP_DATA_TYPE_BFLOAT16, 3, pA, dims, str, box, es,
               CU_TENSOR_MAP_INTERLEAVE_NONE, CU_TENSOR_MAP_SWIZZLE_128B,
               CU_TENSOR_MAP_L2_PROMOTION_L2_128B, CU_TENSOR_MAP_FLOAT_OOB_FILL_NONE);
    }
    {
        cuuint64_t dims[3] = {KTOT, NCOLS, 1};
        cuuint64_t str[2]  = {KTOT * 2ull, (cuuint64_t)NCOLS * KTOT * 2ull};
        cuuint32_t box[3]  = {KB, TN, 1};
        cuuint32_t es[3]   = {1, 1, 1};
        encode(&tmB, CU_TENSOR_MAP_DATA_TYPE_BFLOAT16, 3, pB, dims, str, box, es,
               CU_TENSOR_MAP_INTERLEAVE_NONE, CU_TENSOR_MAP_SWIZZLE_128B,
               CU_TENSOR_MAP_L2_PROMOTION_L2_128B, CU_TENSOR_MAP_FLOAT_OOB_FILL_NONE);
    }

    cudaFuncSetAttribute(gemm_kernel, cudaFuncAttributeMaxDynamicSharedMemorySize, SMEM_DYN);
    dim3 grid(N_TILES, M_TILES);
    gemm_kernel<<<grid, 256, SMEM_DYN>>>(out, tmA, tmB);
}

// round 8
// speedup vs baseline: 1.4940x; 1.4940x over previous
#include <cuda_runtime.h>
#include <cuda.h>
#include <cuda_fp16.h>
#include <cstdint>

// ---------------------------------------------------------------------------
// Problem constants
// ---------------------------------------------------------------------------
#define NROWS   100000
#define INCH    512
#define OUTCH   512
#define KTOT    2048            // 4 segments * 512 : [x_re,x_im,x_re,x_im]·[Wh,Vh,Wl,Vl]
#define NCOLS   1024            // out_re (512) ++ out_im (512)

#define TM      128             // CTA tile M
#define TN      128             // CTA tile N
#define KB      64              // fp16 elems per K-block (128 bytes = SW128 row)
#define STAGES  4
#define NITERS  32              // 4 segs * (512/64)

#define M_TILES 782             // ceil(100000/128)
#define N_TILES 8               // 1024/128

// SMEM layout (relative to 1024-aligned base)
#define OFF_FULL   0            // 4 full mbarriers (8B each)
#define OFF_STAGE0 1024
#define A_BYTES    (TM * KB * 2)          // 16384
#define B_BYTES    (TN * KB * 2)          // 16384
#define STAGE_BYTES (A_BYTES + B_BYTES)   // 32768
#define SMEM_DYN   (1024 /*align slack*/ + 1024 + STAGES * STAGE_BYTES)  // 133120

// ---------------------------------------------------------------------------
// Device scratch (allocation-free rule: __device__ globals)
// ---------------------------------------------------------------------------
// A planes: 0 = x_re, 1 = x_im ; each [NROWS][INCH] fp16 (single-precision fp16 x)
__device__ __half g_A[2ull * NROWS * INCH];
// B: [NCOLS][KTOT] fp16, K-major. Segments: [Wh, Vh, Wl, Vl]
//   o <  512 (out_re): W = Re,  V = -Im
//   o >= 512 (out_im): W = Im,  V =  Re
__device__ __half g_B[(size_t)NCOLS * KTOT];

// ---------------------------------------------------------------------------
// PTX helpers (generic-PTX only: no tcgen05 / TMEM / cta_group)
// ---------------------------------------------------------------------------
__device__ __forceinline__ uint32_t smem_u32(const void* p) {
    uint32_t a;
    asm("{ .reg .u64 t; cvta.to.shared.u64 t, %1; cvt.u32.u64 %0, t; }" : "=r"(a) : "l"(p));
    return a;
}
__device__ __forceinline__ uint32_t h2_as_u32(__half2 h) {
    union { __half2 h; uint32_t u; } cvt;
    cvt.h = h;
    return cvt.u;
}
#define MBARRIER_INIT(addr, cnt) \
    asm volatile("mbarrier.init.shared.b64 [%0], %1;" :: "r"((uint32_t)(addr)), "r"((uint32_t)(cnt)) : "memory")
#define MBARRIER_EXPECT_TX(addr, bytes) \
    asm volatile("mbarrier.arrive.expect_tx.shared.b64 _, [%0], %1;" :: "r"((uint32_t)(addr)), "r"((uint32_t)(bytes)) : "memory")
#define FENCE_PROXY_ASYNC_SHARED_CTA() \
    asm volatile("fence.proxy.async.shared::cta;" ::: "memory")

#define MBARRIER_WAIT_PARITY(mbar_smem_addr, phase_parity) do { \
    uint32_t _mbar = (uint32_t)(mbar_smem_addr); \
    uint32_t _parity = (uint32_t)(phase_parity); \
    uint32_t _done; \
    asm volatile("{\n\t.reg .pred p;\n\t" \
        "mbarrier.try_wait.parity.acquire.cta.shared::cta.b64 p, [%1], %2;\n\t" \
        "selp.b32 %0, 1, 0, p;\n\t}" : "=r"(_done) : "r"(_mbar), "r"(_parity) : "memory"); \
    if (!_done) { \
        asm volatile("{\n\t.reg .pred P1;\n\t" \
            "WAIT_LOOP_%=:\n\t" \
            "mbarrier.try_wait.parity.acquire.cta.shared::cta.b64 P1, [%0], %1, 0x989680;\n\t" \
            "@P1 bra.uni WAIT_DONE_%=;\n\t" \
            "bra.uni WAIT_LOOP_%=;\n\t" \
            "WAIT_DONE_%=:\n\t}" :: "r"(_mbar), "r"(_parity) : "memory"); \
    } \
} while(0)

#define TMA_LOAD_3D(smem_addr, tmap, cx, cy, cz, mbar) \
    asm volatile("cp.async.bulk.tensor.3d.shared::cta.global.tile.mbarrier::complete_tx::bytes " \
        "[%0], [%1, {%2, %3, %4}], [%5];" \
        :: "r"((uint32_t)(smem_addr)), "l"(tmap), "r"((int32_t)(cx)), "r"((int32_t)(cy)), "r"((int32_t)(cz)), \
           "r"((uint32_t)(mbar)) : "memory")

#define LDSM_X4(r0, r1, r2, r3, addr) \
    asm volatile("ldmatrix.sync.aligned.m8n8.x4.shared.b16 {%0,%1,%2,%3}, [%4];" \
        : "=r"(r0), "=r"(r1), "=r"(r2), "=r"(r3) : "r"(addr))

#define MMA_16816(c0, c1, c2, c3, a0, a1, a2, a3, b0, b1) \
    asm volatile("mma.sync.aligned.m16n8k16.row.col.f32.f16.f16.f32 " \
        "{%0,%1,%2,%3}, {%4,%5,%6,%7}, {%8,%9}, {%0,%1,%2,%3};" \
        : "+f"(c0), "+f"(c1), "+f"(c2), "+f"(c3) \
        : "r"(a0), "r"(a1), "r"(a2), "r"(a3), "r"(b0), "r"(b1))

// ---------------------------------------------------------------------------
// Prep kernels
// ---------------------------------------------------------------------------
// Convert x_re / x_im to fp16 planes; vectorized: float4 in, 8B out per plane.
__global__ void prep_A_kernel(const float* __restrict__ xre, const float* __restrict__ xim) {
    const size_t P = (size_t)NROWS * INCH;                  // 51,200,000 (divisible by 4)
    size_t i4 = (size_t)blockIdx.x * blockDim.x + threadIdx.x;
    if (i4 * 4 >= P) return;
    float4 vr = reinterpret_cast<const float4*>(xre)[i4];
    float4 vi = reinterpret_cast<const float4*>(xim)[i4];
    uint2 pr = make_uint2(h2_as_u32(__floats2half2_rn(vr.x, vr.y)),
                          h2_as_u32(__floats2half2_rn(vr.z, vr.w)));
    uint2 pi = make_uint2(h2_as_u32(__floats2half2_rn(vi.x, vi.y)),
                          h2_as_u32(__floats2half2_rn(vi.z, vi.w)));
    reinterpret_cast<uint2*>(g_A)[i4] = pr;
    reinterpret_cast<uint2*>(g_A + P)[i4] = pi;
}

// Build B[1024][2048] fp16, segments [Wh, Vh, Wl, Vl]:
//   o <  512 (out_re): W = Re,  V = -Im
//   o >= 512 (out_im): W = Im,  V =  Re
__global__ void prep_B_kernel(const float* __restrict__ Re, const float* __restrict__ Im) {
    int idx = blockIdx.x * blockDim.x + threadIdx.x;
    if (idx >= NCOLS * KTOT) return;
    int o   = idx / KTOT;
    int k   = idx % KTOT;
    int seg = k >> 9;          // 0..3
    int ii  = k & 511;
    bool vsel = (seg & 1);     // odd segments use V
    float w;
    if (o < 512) w = vsel ? -Im[o * 512 + ii] : Re[o * 512 + ii];
    else         w = vsel ?  Re[(o - 512) * 512 + ii] : Im[(o - 512) * 512 + ii];
    __half h = __float2half_rn(w);
    __half v = h;
    if (seg >= 2) v = __float2half_rn(w - __half2float(h));   // lo part
    g_B[idx] = v;
}

// ---------------------------------------------------------------------------
// GEMM kernel: D[m][n] = sum_k A[m][k] * B[n][k]
// CTA tile 128x128, 8 warps (4 along M x 2 along N), warp tile 32x64.
// TMA 4-stage pipeline -> ldmatrix -> mma.sync m16n8k16 fp16, fp32 acc.
// ---------------------------------------------------------------------------
__global__ void __launch_bounds__(256, 1) gemm_kernel(
    float* __restrict__ out,
    const __grid_constant__ CUtensorMap tmA,
    const __grid_constant__ CUtensorMap tmB)
{
    extern __shared__ char smem_raw[];
    const uint32_t base = (smem_u32(smem_raw) + 1023u) & ~1023u;
    const int tid  = threadIdx.x;
    const int wid  = tid >> 5;
    const int lane = tid & 31;
    const int n_tile = blockIdx.x;   // 0..7 (fastest -> A-tile reuse in L2)
    const int m_tile = blockIdx.y;   // 0..781

    const int warp_m = (wid & 3) * 32;   // 0,32,64,96
    const int warp_n = (wid >> 2) * 64;  // 0,64

    if (tid == 0) {
        #pragma unroll
        for (int s = 0; s < STAGES; ++s) MBARRIER_INIT(base + OFF_FULL + s * 8, 1);
        FENCE_PROXY_ASYNC_SHARED_CTA();
    }
    __syncthreads();

    // Prologue: fill all stages (j<8 -> seg==0, plane 0).
    if (tid == 0) {
        #pragma unroll
        for (int j = 0; j < STAGES; ++j) {
            uint32_t full = base + OFF_FULL + j * 8;
            MBARRIER_EXPECT_TX(full, STAGE_BYTES);
            uint32_t a_dst = base + OFF_STAGE0 + j * STAGE_BYTES;
            TMA_LOAD_3D(a_dst, &tmA, j * KB, m_tile * TM, 0, full);
            TMA_LOAD_3D(a_dst + A_BYTES, &tmB, j * KB, n_tile * TN, 0, full);
        }
    }

    // Per-lane row bases and SW128 XOR masks (mask = (row%8)<<4, bits [6:4]).
    // k-chunk byte offset (khalf*16 + ks*32) also lives in bits [6:4], so
    // (koff ^ mask) is carry-free and must be XORed, not added.
    // A: row = warp_m + (lane&15), khalf = lane>>4
    const uint32_t a_row   = (uint32_t)(warp_m + (lane & 15));
    const uint32_t a_rowba = base + OFF_STAGE0 + a_row * 128u;
    const uint32_t a_mask  = (a_row & 7u) << 4;
    const uint32_t a_kh    = (uint32_t)(lane >> 4) * 16u;
    // B: row = warp_n + (lane&7) + (lane>>4)*8, khalf = (lane>>3)&1
    const uint32_t b_row   = (uint32_t)(warp_n + (lane & 7) + ((lane >> 4) << 3));
    const uint32_t b_rowba = base + OFF_STAGE0 + A_BYTES + b_row * 128u;
    const uint32_t b_mask  = (b_row & 7u) << 4;
    const uint32_t b_kh    = (uint32_t)((lane >> 3) & 1) * 16u;

    float acc[2][8][4];
    #pragma unroll
    for (int mi = 0; mi < 2; ++mi)
        #pragma unroll
        for (int ni = 0; ni < 8; ++ni)
            #pragma unroll
            for (int r = 0; r < 4; ++r) acc[mi][ni][r] = 0.0f;

    for (int it = 0; it < NITERS; ++it) {
        const int s  = it & (STAGES - 1);
        const int ph = (it >> 2) & 1;
        MBARRIER_WAIT_PARITY(base + OFF_FULL + s * 8, ph);

        const uint32_t a_st = a_rowba + s * STAGE_BYTES;
        const uint32_t b_st = b_rowba + s * STAGE_BYTES;

        #pragma unroll
        for (int ks = 0; ks < 4; ++ks) {
            const uint32_t a_ko = (a_kh + (uint32_t)ks * 32u) ^ a_mask;
            const uint32_t b_ko = (b_kh + (uint32_t)ks * 32u) ^ b_mask;
            uint32_t a[2][4];
            #pragma unroll
            for (int mi = 0; mi < 2; ++mi)
                LDSM_X4(a[mi][0], a[mi][1], a[mi][2], a[mi][3],
                        a_st + mi * 2048 + a_ko);
            uint32_t b[4][4];
            #pragma unroll
            for (int ni2 = 0; ni2 < 4; ++ni2)
                LDSM_X4(b[ni2][0], b[ni2][1], b[ni2][2], b[ni2][3],
                        b_st + ni2 * 2048 + b_ko);
            #pragma unroll
            for (int mi = 0; mi < 2; ++mi)
                #pragma unroll
                for (int ni = 0; ni < 8; ++ni) {
                    const int ni2 = ni >> 1;
                    const int h   = (ni & 1) * 2;   // 0 -> regs {0,1}, 1 -> {2,3}
                    MMA_16816(acc[mi][ni][0], acc[mi][ni][1], acc[mi][ni][2], acc[mi][ni][3],
                              a[mi][0], a[mi][1], a[mi][2], a[mi][3],
                              b[ni2][h], b[ni2][h + 1]);
                }
        }

        __syncthreads();   // all warps done reading stage s
        if (tid == 0 && it + STAGES < NITERS) {
            const int j = it + STAGES;
            const int seg = j >> 3, kb = j & 7;
            const int plane = seg & 1;            // segs: [x_re, x_im, x_re, x_im]
            uint32_t full = base + OFF_FULL + s * 8;
            MBARRIER_EXPECT_TX(full, STAGE_BYTES);
            uint32_t a_dst = base + OFF_STAGE0 + s * STAGE_BYTES;
            TMA_LOAD_3D(a_dst, &tmA, kb * KB, m_tile * TM, plane, full);
            TMA_LOAD_3D(a_dst + A_BYTES, &tmB, seg * 512 + kb * KB, n_tile * TN, 0, full);
        }
    }

    // ---- Epilogue: fragments -> GMEM ----
    // D frag m16n8: {c0,c1} at row lane/4, cols 2*(lane%4)+{0,1}; {c2,c3} at row+8.
    const int m_base = m_tile * TM + warp_m;
    const int n_base = n_tile * TN + warp_n;
    #pragma unroll
    for (int mi = 0; mi < 2; ++mi) {
        #pragma unroll
        for (int ni = 0; ni < 8; ++ni) {
            int r0 = m_base + mi * 16 + (lane >> 2);
            int c  = n_base + ni * 8 + (lane & 3) * 2;
            int plane = c >> 9;
            int col   = c & 511;
            float* p = out + (size_t)plane * ((size_t)NROWS * OUTCH) + (size_t)r0 * OUTCH + col;
            if (r0 < NROWS)
                *reinterpret_cast<float2*>(p) = make_float2(acc[mi][ni][0], acc[mi][ni][1]);
            if (r0 + 8 < NROWS)
                *reinterpret_cast<float2*>(p + 8 * OUTCH) = make_float2(acc[mi][ni][2], acc[mi][ni][3]);
        }
    }
}

// ---------------------------------------------------------------------------
// Host launch
// ---------------------------------------------------------------------------
typedef CUresult (*EncodeTiledFn)(
    CUtensorMap*, CUtensorMapDataType, cuuint32_t, void*,
    const cuuint64_t*, const cuuint64_t*, const cuuint32_t*, const cuuint32_t*,
    CUtensorMapInterleave, CUtensorMapSwizzle, CUtensorMapL2promotion, CUtensorMapFloatOOBfill);

extern "C" void kernel_launch(void* const* d_in, const int* in_sizes, int n_in,
                              void* d_out, int out_size) {
    const float* x_re = (const float*)d_in[0];
    const float* x_im = (const float*)d_in[1];
    const float* Re   = (const float*)d_in[2];
    const float* Im   = (const float*)d_in[3];
    float* out = (float*)d_out;

    void *pA = nullptr, *pB = nullptr;
    cudaGetSymbolAddress(&pA, g_A);
    cudaGetSymbolAddress(&pB, g_B);

    const size_t P = (size_t)NROWS * INCH;
    prep_A_kernel<<<(unsigned)((P / 4 + 255) / 256), 256>>>(x_re, x_im);
    prep_B_kernel<<<(NCOLS * KTOT + 255) / 256, 256>>>(Re, Im);

    EncodeTiledFn encode = nullptr;
    cudaDriverEntryPointQueryResult qr;
    cudaGetDriverEntryPointByVersion("cuTensorMapEncodeTiled", (void**)&encode,
                                     12000, cudaEnableDefault, &qr);
    if (!encode) return;

    CUtensorMap tmA{}, tmB{};
    {
        cuuint64_t dims[3] = {INCH, NROWS, 2};
        cuuint64_t str[2]  = {INCH * 2ull, (cuuint64_t)NROWS * INCH * 2ull};
        cuuint32_t box[3]  = {KB, TM, 1};
        cuuint32_t es[3]   = {1, 1, 1};
        encode(&tmA, CU_TENSOR_MAP_DATA_TYPE_FLOAT16, 3, pA, dims, str, box, es,
               CU_TENSOR_MAP_INTERLEAVE_NONE, CU_TENSOR_MAP_SWIZZLE_128B,
               CU_TENSOR_MAP_L2_PROMOTION_L2_128B, CU_TENSOR_MAP_FLOAT_OOB_FILL_NONE);
    }
    {
        cuuint64_t dims[3] = {KTOT, NCOLS, 1};
        cuuint64_t str[2]  = {KTOT * 2ull, (cuuint64_t)NCOLS * KTOT * 2ull};
        cuuint32_t box[3]  = {KB, TN, 1};
        cuuint32_t es[3]   = {1, 1, 1};
        encode(&tmB, CU_TENSOR_MAP_DATA_TYPE_FLOAT16, 3, pB, dims, str, box, es,
               CU_TENSOR_MAP_INTERLEAVE_NONE, CU_TENSOR_MAP_SWIZZLE_128B,
               CU_TENSOR_MAP_L2_PROMOTION_L2_128B, CU_TENSOR_MAP_FLOAT_OOB_FILL_NONE);
    }

    cudaFuncSetAttribute(gemm_kernel, cudaFuncAttributeMaxDynamicSharedMemorySize, SMEM_DYN);
    dim3 grid(N_TILES, M_TILES);
    gemm_kernel<<<grid, 256, SMEM_DYN>>>(out, tmA, tmB);
}

// round 10
// speedup vs baseline: 2.5433x; 1.7023x over previous
#include <cuda_runtime.h>
#include <cuda.h>
#include <cuda_fp16.h>
#include <cstdint>

// ---------------------------------------------------------------------------
// Problem constants
// ---------------------------------------------------------------------------
#define NROWS   100000
#define INCH    512
#define OUTCH   512
#define KTOT    1024            // 2 segments * 512 : [x_re,x_im]·[W,V], all single fp16
#define NCOLS   1024            // out_re (512) ++ out_im (512)

#define TM      128             // CTA tile M
#define TN      128             // CTA tile N
#define KB      64              // fp16 elems per K-block (128 bytes = SW128 row)
#define STAGES  4
#define NITERS  16              // 2 segs * (512/64)

#define M_TILES 782             // ceil(100000/128)
#define N_TILES 8               // 1024/128

// SMEM layout (relative to 1024-aligned base)
#define OFF_FULL   0            // 4 full mbarriers (8B each)
#define OFF_STAGE0 1024
#define A_BYTES    (TM * KB * 2)          // 16384
#define B_BYTES    (TN * KB * 2)          // 16384
#define STAGE_BYTES (A_BYTES + B_BYTES)   // 32768
#define SMEM_DYN   (1024 /*align slack*/ + 1024 + STAGES * STAGE_BYTES)  // 133120

// ---------------------------------------------------------------------------
// Device scratch (allocation-free rule: __device__ globals)
// ---------------------------------------------------------------------------
// A planes: 0 = x_re, 1 = x_im ; each [NROWS][INCH] fp16
__device__ __half g_A[2ull * NROWS * INCH];
// B: [NCOLS][KTOT] fp16, K-major. Segments: [W, V]
//   o <  512 (out_re): W = Re,  V = -Im
//   o >= 512 (out_im): W = Im,  V =  Re
__device__ __half g_B[(size_t)NCOLS * KTOT];

// ---------------------------------------------------------------------------
// PTX helpers (generic-PTX only: no tcgen05 / TMEM / cta_group)
// ---------------------------------------------------------------------------
__device__ __forceinline__ uint32_t smem_u32(const void* p) {
    uint32_t a;
    asm("{ .reg .u64 t; cvta.to.shared.u64 t, %1; cvt.u32.u64 %0, t; }" : "=r"(a) : "l"(p));
    return a;
}
__device__ __forceinline__ uint32_t h2_as_u32(__half2 h) {
    union { __half2 h; uint32_t u; } cvt;
    cvt.h = h;
    return cvt.u;
}
#define MBARRIER_INIT(addr, cnt) \
    asm volatile("mbarrier.init.shared.b64 [%0], %1;" :: "r"((uint32_t)(addr)), "r"((uint32_t)(cnt)) : "memory")
#define MBARRIER_EXPECT_TX(addr, bytes) \
    asm volatile("mbarrier.arrive.expect_tx.shared.b64 _, [%0], %1;" :: "r"((uint32_t)(addr)), "r"((uint32_t)(bytes)) : "memory")
#define FENCE_PROXY_ASYNC_SHARED_CTA() \
    asm volatile("fence.proxy.async.shared::cta;" ::: "memory")

#define MBARRIER_WAIT_PARITY(mbar_smem_addr, phase_parity) do { \
    uint32_t _mbar = (uint32_t)(mbar_smem_addr); \
    uint32_t _parity = (uint32_t)(phase_parity); \
    uint32_t _done; \
    asm volatile("{\n\t.reg .pred p;\n\t" \
        "mbarrier.try_wait.parity.acquire.cta.shared::cta.b64 p, [%1], %2;\n\t" \
        "selp.b32 %0, 1, 0, p;\n\t}" : "=r"(_done) : "r"(_mbar), "r"(_parity) : "memory"); \
    if (!_done) { \
        asm volatile("{\n\t.reg .pred P1;\n\t" \
            "WAIT_LOOP_%=:\n\t" \
            "mbarrier.try_wait.parity.acquire.cta.shared::cta.b64 P1, [%0], %1, 0x989680;\n\t" \
            "@P1 bra.uni WAIT_DONE_%=;\n\t" \
            "bra.uni WAIT_LOOP_%=;\n\t" \
            "WAIT_DONE_%=:\n\t}" :: "r"(_mbar), "r"(_parity) : "memory"); \
    } \
} while(0)

#define TMA_LOAD_3D(smem_addr, tmap, cx, cy, cz, mbar) \
    asm volatile("cp.async.bulk.tensor.3d.shared::cta.global.tile.mbarrier::complete_tx::bytes " \
        "[%0], [%1, {%2, %3, %4}], [%5];" \
        :: "r"((uint32_t)(smem_addr)), "l"(tmap), "r"((int32_t)(cx)), "r"((int32_t)(cy)), "r"((int32_t)(cz)), \
           "r"((uint32_t)(mbar)) : "memory")

#define LDSM_X4(r0, r1, r2, r3, addr) \
    asm volatile("ldmatrix.sync.aligned.m8n8.x4.shared.b16 {%0,%1,%2,%3}, [%4];" \
        : "=r"(r0), "=r"(r1), "=r"(r2), "=r"(r3) : "r"(addr))

#define MMA_16816(c0, c1, c2, c3, a0, a1, a2, a3, b0, b1) \
    asm volatile("mma.sync.aligned.m16n8k16.row.col.f32.f16.f16.f32 " \
        "{%0,%1,%2,%3}, {%4,%5,%6,%7}, {%8,%9}, {%0,%1,%2,%3};" \
        : "+f"(c0), "+f"(c1), "+f"(c2), "+f"(c3) \
        : "r"(a0), "r"(a1), "r"(a2), "r"(a3), "r"(b0), "r"(b1))

// ---------------------------------------------------------------------------
// Prep kernels
// ---------------------------------------------------------------------------
// Convert x_re / x_im to fp16 planes; vectorized: float4 in, 8B out per plane.
__global__ void prep_A_kernel(const float* __restrict__ xre, const float* __restrict__ xim) {
    const size_t P = (size_t)NROWS * INCH;                  // 51,200,000 (divisible by 4)
    size_t i4 = (size_t)blockIdx.x * blockDim.x + threadIdx.x;
    if (i4 * 4 >= P) return;
    float4 vr = reinterpret_cast<const float4*>(xre)[i4];
    float4 vi = reinterpret_cast<const float4*>(xim)[i4];
    uint2 pr = make_uint2(h2_as_u32(__floats2half2_rn(vr.x, vr.y)),
                          h2_as_u32(__floats2half2_rn(vr.z, vr.w)));
    uint2 pi = make_uint2(h2_as_u32(__floats2half2_rn(vi.x, vi.y)),
                          h2_as_u32(__floats2half2_rn(vi.z, vi.w)));
    reinterpret_cast<uint2*>(g_A)[i4] = pr;
    reinterpret_cast<uint2*>(g_A + P)[i4] = pi;
}

// Build B[1024][1024] fp16, segments [W, V]:
//   o <  512 (out_re): W = Re,  V = -Im
//   o >= 512 (out_im): W = Im,  V =  Re
__global__ void prep_B_kernel(const float* __restrict__ Re, const float* __restrict__ Im) {
    int idx = blockIdx.x * blockDim.x + threadIdx.x;
    if (idx >= NCOLS * KTOT) return;
    int o   = idx / KTOT;
    int k   = idx % KTOT;
    int seg = k >> 9;          // 0..1
    int ii  = k & 511;
    float w;
    if (o < 512) w = seg ? -Im[o * 512 + ii] : Re[o * 512 + ii];
    else         w = seg ?  Re[(o - 512) * 512 + ii] : Im[(o - 512) * 512 + ii];
    g_B[idx] = __float2half_rn(w);
}

// ---------------------------------------------------------------------------
// GEMM kernel: D[m][n] = sum_k A[m][k] * B[n][k]
// CTA tile 128x128, 8 warps (4 along M x 2 along N), warp tile 32x64.
// TMA 4-stage pipeline -> ldmatrix -> mma.sync m16n8k16 fp16, fp32 acc.
// ---------------------------------------------------------------------------
__global__ void __launch_bounds__(256, 1) gemm_kernel(
    float* __restrict__ out,
    const __grid_constant__ CUtensorMap tmA,
    const __grid_constant__ CUtensorMap tmB)
{
    extern __shared__ char smem_raw[];
    const uint32_t base = (smem_u32(smem_raw) + 1023u) & ~1023u;
    const int tid  = threadIdx.x;
    const int wid  = tid >> 5;
    const int lane = tid & 31;
    const int n_tile = blockIdx.x;   // 0..7 (fastest -> A-tile reuse in L2)
    const int m_tile = blockIdx.y;   // 0..781

    const int warp_m = (wid & 3) * 32;   // 0,32,64,96
    const int warp_n = (wid >> 2) * 64;  // 0,64

    if (tid == 0) {
        #pragma unroll
        for (int s = 0; s < STAGES; ++s) MBARRIER_INIT(base + OFF_FULL + s * 8, 1);
        FENCE_PROXY_ASYNC_SHARED_CTA();
    }
    __syncthreads();

    // Prologue: fill all stages (j<8 -> seg==0, plane 0).
    if (tid == 0) {
        #pragma unroll
        for (int j = 0; j < STAGES; ++j) {
            uint32_t full = base + OFF_FULL + j * 8;
            MBARRIER_EXPECT_TX(full, STAGE_BYTES);
            uint32_t a_dst = base + OFF_STAGE0 + j * STAGE_BYTES;
            TMA_LOAD_3D(a_dst, &tmA, j * KB, m_tile * TM, 0, full);
            TMA_LOAD_3D(a_dst + A_BYTES, &tmB, j * KB, n_tile * TN, 0, full);
        }
    }

    // Per-lane row bases and SW128 XOR masks (mask = (row%8)<<4, bits [6:4]).
    // k-chunk byte offset (khalf*16 + ks*32) also lives in bits [6:4], so
    // (koff ^ mask) is carry-free and must be XORed, not added.
    // A: row = warp_m + (lane&15), khalf = lane>>4
    const uint32_t a_row   = (uint32_t)(warp_m + (lane & 15));
    const uint32_t a_rowba = base + OFF_STAGE0 + a_row * 128u;
    const uint32_t a_mask  = (a_row & 7u) << 4;
    const uint32_t a_kh    = (uint32_t)(lane >> 4) * 16u;
    // B: row = warp_n + (lane&7) + (lane>>4)*8, khalf = (lane>>3)&1
    const uint32_t b_row   = (uint32_t)(warp_n + (lane & 7) + ((lane >> 4) << 3));
    const uint32_t b_rowba = base + OFF_STAGE0 + A_BYTES + b_row * 128u;
    const uint32_t b_mask  = (b_row & 7u) << 4;
    const uint32_t b_kh    = (uint32_t)((lane >> 3) & 1) * 16u;

    float acc[2][8][4];
    #pragma unroll
    for (int mi = 0; mi < 2; ++mi)
        #pragma unroll
        for (int ni = 0; ni < 8; ++ni)
            #pragma unroll
            for (int r = 0; r < 4; ++r) acc[mi][ni][r] = 0.0f;

    for (int it = 0; it < NITERS; ++it) {
        const int s  = it & (STAGES - 1);
        const int ph = (it >> 2) & 1;
        MBARRIER_WAIT_PARITY(base + OFF_FULL + s * 8, ph);

        const uint32_t a_st = a_rowba + s * STAGE_BYTES;
        const uint32_t b_st = b_rowba + s * STAGE_BYTES;

        #pragma unroll
        for (int ks = 0; ks < 4; ++ks) {
            const uint32_t a_ko = (a_kh + (uint32_t)ks * 32u) ^ a_mask;
            const uint32_t b_ko = (b_kh + (uint32_t)ks * 32u) ^ b_mask;
            uint32_t a[2][4];
            #pragma unroll
            for (int mi = 0; mi < 2; ++mi)
                LDSM_X4(a[mi][0], a[mi][1], a[mi][2], a[mi][3],
                        a_st + mi * 2048 + a_ko);
            uint32_t b[4][4];
            #pragma unroll
            for (int ni2 = 0; ni2 < 4; ++ni2)
                LDSM_X4(b[ni2][0], b[ni2][1], b[ni2][2], b[ni2][3],
                        b_st + ni2 * 2048 + b_ko);
            #pragma unroll
            for (int mi = 0; mi < 2; ++mi)
                #pragma unroll
                for (int ni = 0; ni < 8; ++ni) {
                    const int ni2 = ni >> 1;
                    const int h   = (ni & 1) * 2;   // 0 -> regs {0,1}, 1 -> {2,3}
                    MMA_16816(acc[mi][ni][0], acc[mi][ni][1], acc[mi][ni][2], acc[mi][ni][3],
                              a[mi][0], a[mi][1], a[mi][2], a[mi][3],
                              b[ni2][h], b[ni2][h + 1]);
                }
        }

        __syncthreads();   // all warps done reading stage s
        if (tid == 0 && it + STAGES < NITERS) {
            const int j = it + STAGES;
            const int seg = j >> 3, kb = j & 7;
            const int plane = seg & 1;            // segs: [x_re, x_im]
            uint32_t full = base + OFF_FULL + s * 8;
            MBARRIER_EXPECT_TX(full, STAGE_BYTES);
            uint32_t a_dst = base + OFF_STAGE0 + s * STAGE_BYTES;
            TMA_LOAD_3D(a_dst, &tmA, kb * KB, m_tile * TM, plane, full);
            TMA_LOAD_3D(a_dst + A_BYTES, &tmB, seg * 512 + kb * KB, n_tile * TN, 0, full);
        }
    }

    // ---- Epilogue: fragments -> GMEM ----
    // D frag m16n8: {c0,c1} at row lane/4, cols 2*(lane%4)+{0,1}; {c2,c3} at row+8.
    const int m_base = m_tile * TM + warp_m;
    const int n_base = n_tile * TN + warp_n;
    #pragma unroll
    for (int mi = 0; mi < 2; ++mi) {
        #pragma unroll
        for (int ni = 0; ni < 8; ++ni) {
            int r0 = m_base + mi * 16 + (lane >> 2);
            int c  = n_base + ni * 8 + (lane & 3) * 2;
            int plane = c >> 9;
            int col   = c & 511;
            float* p = out + (size_t)plane * ((size_t)NROWS * OUTCH) + (size_t)r0 * OUTCH + col;
            if (r0 < NROWS)
                *reinterpret_cast<float2*>(p) = make_float2(acc[mi][ni][0], acc[mi][ni][1]);
            if (r0 + 8 < NROWS)
                *reinterpret_cast<float2*>(p + 8 * OUTCH) = make_float2(acc[mi][ni][2], acc[mi][ni][3]);
        }
    }
}

// ---------------------------------------------------------------------------
// Host launch
// ---------------------------------------------------------------------------
typedef CUresult (*EncodeTiledFn)(
    CUtensorMap*, CUtensorMapDataType, cuuint32_t, void*,
    const cuuint64_t*, const cuuint64_t*, const cuuint32_t*, const cuuint32_t*,
    CUtensorMapInterleave, CUtensorMapSwizzle, CUtensorMapL2promotion, CUtensorMapFloatOOBfill);

extern "C" void kernel_launch(void* const* d_in, const int* in_sizes, int n_in,
                              void* d_out, int out_size) {
    const float* x_re = (const float*)d_in[0];
    const float* x_im = (const float*)d_in[1];
    const float* Re   = (const float*)d_in[2];
    const float* Im   = (const float*)d_in[3];
    float* out = (float*)d_out;

    void *pA = nullptr, *pB = nullptr;
    cudaGetSymbolAddress(&pA, g_A);
    cudaGetSymbolAddress(&pB, g_B);

    const size_t P = (size_t)NROWS * INCH;
    prep_A_kernel<<<(unsigned)((P / 4 + 255) / 256), 256>>>(x_re, x_im);
    prep_B_kernel<<<(NCOLS * KTOT + 255) / 256, 256>>>(Re, Im);

    EncodeTiledFn encode = nullptr;
    cudaDriverEntryPointQueryResult qr;
    cudaGetDriverEntryPointByVersion("cuTensorMapEncodeTiled", (void**)&encode,
                                     12000, cudaEnableDefault, &qr);
    if (!encode) return;

    CUtensorMap tmA{}, tmB{};
    {
        cuuint64_t dims[3] = {INCH, NROWS, 2};
        cuuint64_t str[2]  = {INCH * 2ull, (cuuint64_t)NROWS * INCH * 2ull};
        cuuint32_t box[3]  = {KB, TM, 1};
        cuuint32_t es[3]   = {1, 1, 1};
        encode(&tmA, CU_TENSOR_MAP_DATA_TYPE_FLOAT16, 3, pA, dims, str, box, es,
               CU_TENSOR_MAP_INTERLEAVE_NONE, CU_TENSOR_MAP_SWIZZLE_128B,
               CU_TENSOR_MAP_L2_PROMOTION_L2_128B, CU_TENSOR_MAP_FLOAT_OOB_FILL_NONE);
    }
    {
        cuuint64_t dims[3] = {KTOT, NCOLS, 1};
        cuuint64_t str[2]  = {KTOT * 2ull, (cuuint64_t)NCOLS * KTOT * 2ull};
        cuuint32_t box[3]  = {KB, TN, 1};
        cuuint32_t es[3]   = {1, 1, 1};
        encode(&tmB, CU_TENSOR_MAP_DATA_TYPE_FLOAT16, 3, pB, dims, str, box, es,
               CU_TENSOR_MAP_INTERLEAVE_NONE, CU_TENSOR_MAP_SWIZZLE_128B,
               CU_TENSOR_MAP_L2_PROMOTION_L2_128B, CU_TENSOR_MAP_FLOAT_OOB_FILL_NONE);
    }

    cudaFuncSetAttribute(gemm_kernel, cudaFuncAttributeMaxDynamicSharedMemorySize, SMEM_DYN);
    dim3 grid(N_TILES, M_TILES);
    gemm_kernel<<<grid, 256, SMEM_DYN>>>(out, tmA, tmB);
}

// round 14
// speedup vs baseline: 2.9966x; 1.1782x over previous
#include <cuda_runtime.h>
#include <cuda.h>
#include <cuda_fp16.h>
#include <cstdint>

// ---------------------------------------------------------------------------
// Problem constants
// ---------------------------------------------------------------------------
#define NROWS   100000
#define INCH    512
#define OUTCH   512
#define KTOT    1024            // 2 segments * 512 : [x_re,x_im]·[W,V], all single fp16
#define NCOLS   1024            // out_re (512) ++ out_im (512)

#define TM      128             // CTA tile M
#define TN      128             // CTA tile N
#define KB      64              // fp16 elems per K-block (128 bytes = SW128 row)
#define STAGES  3               // 3 stages -> 99.3KB SMEM -> 2 CTAs/SM
#define NITERS  16              // 2 segs * (512/64)

#define M_TILES 782             // ceil(100000/128)
#define N_TILES 8               // 1024/128

// SMEM layout (relative to 1024-aligned base)
#define OFF_FULL   0            // 3 full mbarriers (8B each)
#define OFF_STAGE0 1024
#define A_BYTES    (TM * KB * 2)          // 16384
#define B_BYTES    (TN * KB * 2)          // 16384
#define STAGE_BYTES (A_BYTES + B_BYTES)   // 32768
#define SMEM_DYN   (1024 /*align slack*/ + 1024 + STAGES * STAGE_BYTES)  // 100352

// ---------------------------------------------------------------------------
// Device scratch (allocation-free rule: __device__ globals)
// ---------------------------------------------------------------------------
// A planes: 0 = x_re, 1 = x_im ; each [NROWS][INCH] fp16
__device__ __half g_A[2ull * NROWS * INCH];
// B: [NCOLS][KTOT] fp16, K-major. Segments: [W, V]
//   o <  512 (out_re): W = Re,  V = -Im
//   o >= 512 (out_im): W = Im,  V =  Re
__device__ __half g_B[(size_t)NCOLS * KTOT];

// ---------------------------------------------------------------------------
// PTX helpers (generic-PTX only: no tcgen05 / TMEM / cta_group)
// ---------------------------------------------------------------------------
__device__ __forceinline__ uint32_t smem_u32(const void* p) {
    uint32_t a;
    asm("{ .reg .u64 t; cvta.to.shared.u64 t, %1; cvt.u32.u64 %0, t; }" : "=r"(a) : "l"(p));
    return a;
}
__device__ __forceinline__ uint32_t h2_as_u32(__half2 h) {
    union { __half2 h; uint32_t u; } cvt;
    cvt.h = h;
    return cvt.u;
}
#define MBARRIER_INIT(addr, cnt) \
    asm volatile("mbarrier.init.shared.b64 [%0], %1;" :: "r"((uint32_t)(addr)), "r"((uint32_t)(cnt)) : "memory")
#define MBARRIER_EXPECT_TX(addr, bytes) \
    asm volatile("mbarrier.arrive.expect_tx.shared.b64 _, [%0], %1;" :: "r"((uint32_t)(addr)), "r"((uint32_t)(bytes)) : "memory")
#define FENCE_PROXY_ASYNC_SHARED_CTA() \
    asm volatile("fence.proxy.async.shared::cta;" ::: "memory")

#define MBARRIER_WAIT_PARITY(mbar_smem_addr, phase_parity) do { \
    uint32_t _mbar = (uint32_t)(mbar_smem_addr); \
    uint32_t _parity = (uint32_t)(phase_parity); \
    uint32_t _done; \
    asm volatile("{\n\t.reg .pred p;\n\t" \
        "mbarrier.try_wait.parity.acquire.cta.shared::cta.b64 p, [%1], %2;\n\t" \
        "selp.b32 %0, 1, 0, p;\n\t}" : "=r"(_done) : "r"(_mbar), "r"(_parity) : "memory"); \
    if (!_done) { \
        asm volatile("{\n\t.reg .pred P1;\n\t" \
            "WAIT_LOOP_%=:\n\t" \
            "mbarrier.try_wait.parity.acquire.cta.shared::cta.b64 P1, [%0], %1, 0x989680;\n\t" \
            "@P1 bra.uni WAIT_DONE_%=;\n\t" \
            "bra.uni WAIT_LOOP_%=;\n\t" \
            "WAIT_DONE_%=:\n\t}" :: "r"(_mbar), "r"(_parity) : "memory"); \
    } \
} while(0)

#define TMA_LOAD_3D(smem_addr, tmap, cx, cy, cz, mbar) \
    asm volatile("cp.async.bulk.tensor.3d.shared::cta.global.tile.mbarrier::complete_tx::bytes " \
        "[%0], [%1, {%2, %3, %4}], [%5];" \
        :: "r"((uint32_t)(smem_addr)), "l"(tmap), "r"((int32_t)(cx)), "r"((int32_t)(cy)), "r"((int32_t)(cz)), \
           "r"((uint32_t)(mbar)) : "memory")

#define LDSM_X4(r0, r1, r2, r3, addr) \
    asm volatile("ldmatrix.sync.aligned.m8n8.x4.shared.b16 {%0,%1,%2,%3}, [%4];" \
        : "=r"(r0), "=r"(r1), "=r"(r2), "=r"(r3) : "r"(addr))

#define MMA_16816(c0, c1, c2, c3, a0, a1, a2, a3, b0, b1) \
    asm volatile("mma.sync.aligned.m16n8k16.row.col.f32.f16.f16.f32 " \
        "{%0,%1,%2,%3}, {%4,%5,%6,%7}, {%8,%9}, {%0,%1,%2,%3};" \
        : "+f"(c0), "+f"(c1), "+f"(c2), "+f"(c3) \
        : "r"(a0), "r"(a1), "r"(a2), "r"(a3), "r"(b0), "r"(b1))

// ---------------------------------------------------------------------------
// Prep kernels
// ---------------------------------------------------------------------------
// Convert x_re / x_im to fp16 planes; vectorized: float4 in, 8B out per plane.
__global__ void prep_A_kernel(const float* __restrict__ xre, const float* __restrict__ xim) {
    const size_t P = (size_t)NROWS * INCH;                  // 51,200,000 (divisible by 4)
    size_t i4 = (size_t)blockIdx.x * blockDim.x + threadIdx.x;
    if (i4 * 4 >= P) return;
    float4 vr = reinterpret_cast<const float4*>(xre)[i4];
    float4 vi = reinterpret_cast<const float4*>(xim)[i4];
    uint2 pr = make_uint2(h2_as_u32(__floats2half2_rn(vr.x, vr.y)),
                          h2_as_u32(__floats2half2_rn(vr.z, vr.w)));
    uint2 pi = make_uint2(h2_as_u32(__floats2half2_rn(vi.x, vi.y)),
                          h2_as_u32(__floats2half2_rn(vi.z, vi.w)));
    reinterpret_cast<uint2*>(g_A)[i4] = pr;
    reinterpret_cast<uint2*>(g_A + P)[i4] = pi;
}

// Build B[1024][1024] fp16, segments [W, V]:
//   o <  512 (out_re): W = Re,  V = -Im
//   o >= 512 (out_im): W = Im,  V =  Re
__global__ void prep_B_kernel(const float* __restrict__ Re, const float* __restrict__ Im) {
    int idx = blockIdx.x * blockDim.x + threadIdx.x;
    if (idx >= NCOLS * KTOT) return;
    int o   = idx / KTOT;
    int k   = idx % KTOT;
    int seg = k >> 9;          // 0..1
    int ii  = k & 511;
    float w;
    if (o < 512) w = seg ? -Im[o * 512 + ii] : Re[o * 512 + ii];
    else         w = seg ?  Re[(o - 512) * 512 + ii] : Im[(o - 512) * 512 + ii];
    g_B[idx] = __float2half_rn(w);
}

// ---------------------------------------------------------------------------
// GEMM kernel: D[m][n] = sum_k A[m][k] * B[n][k]
// CTA tile 128x128, 8 warps (4 along M x 2 along N), warp tile 32x64.
// TMA 3-stage pipeline -> ldmatrix -> mma.sync m16n8k16 fp16, fp32 acc.
// 2 CTAs/SM: one CTA's sync/prologue/epilogue bubbles hide under the other's MMAs.
// ---------------------------------------------------------------------------
__global__ void __launch_bounds__(256, 2) gemm_kernel(
    float* __restrict__ out,
    const __grid_constant__ CUtensorMap tmA,
    const __grid_constant__ CUtensorMap tmB)
{
    extern __shared__ char smem_raw[];
    const uint32_t base = (smem_u32(smem_raw) + 1023u) & ~1023u;
    const int tid  = threadIdx.x;
    const int wid  = tid >> 5;
    const int lane = tid & 31;
    const int n_tile = blockIdx.x;   // 0..7 (fastest -> A-tile reuse in L2)
    const int m_tile = blockIdx.y;   // 0..781

    const int warp_m = (wid & 3) * 32;   // 0,32,64,96
    const int warp_n = (wid >> 2) * 64;  // 0,64

    if (tid == 0) {
        #pragma unroll
        for (int s = 0; s < STAGES; ++s) MBARRIER_INIT(base + OFF_FULL + s * 8, 1);
        FENCE_PROXY_ASYNC_SHARED_CTA();
    }
    __syncthreads();

    // Prologue: fill all 3 stages (j<8 -> seg==0, plane 0).
    if (tid == 0) {
        #pragma unroll
        for (int j = 0; j < STAGES; ++j) {
            uint32_t full = base + OFF_FULL + j * 8;
            MBARRIER_EXPECT_TX(full, STAGE_BYTES);
            uint32_t a_dst = base + OFF_STAGE0 + j * STAGE_BYTES;
            TMA_LOAD_3D(a_dst, &tmA, j * KB, m_tile * TM, 0, full);
            TMA_LOAD_3D(a_dst + A_BYTES, &tmB, j * KB, n_tile * TN, 0, full);
        }
    }

    // Per-lane row bases and SW128 XOR masks (mask = (row%8)<<4, bits [6:4]).
    // k-chunk byte offset (khalf*16 + ks*32) also lives in bits [6:4], so
    // (koff ^ mask) is carry-free and must be XORed, not added.
    // A: row = warp_m + (lane&15), khalf = lane>>4
    const uint32_t a_row   = (uint32_t)(warp_m + (lane & 15));
    const uint32_t a_rowba = base + OFF_STAGE0 + a_row * 128u;
    const uint32_t a_mask  = (a_row & 7u) << 4;
    const uint32_t a_kh    = (uint32_t)(lane >> 4) * 16u;
    // B: row = warp_n + (lane&7) + (lane>>4)*8, khalf = (lane>>3)&1
    const uint32_t b_row   = (uint32_t)(warp_n + (lane & 7) + ((lane >> 4) << 3));
    const uint32_t b_rowba = base + OFF_STAGE0 + A_BYTES + b_row * 128u;
    const uint32_t b_mask  = (b_row & 7u) << 4;
    const uint32_t b_kh    = (uint32_t)((lane >> 3) & 1) * 16u;

    float acc[2][8][4];
    #pragma unroll
    for (int mi = 0; mi < 2; ++mi)
        #pragma unroll
        for (int ni = 0; ni < 8; ++ni)
            #pragma unroll
            for (int r = 0; r < 4; ++r) acc[mi][ni][r] = 0.0f;

    int s = 0, ph = 0;   // consumer stage/phase (STAGES=3 is not a power of 2)
    for (int it = 0; it < NITERS; ++it) {
        MBARRIER_WAIT_PARITY(base + OFF_FULL + s * 8, ph);

        const uint32_t a_st = a_rowba + s * STAGE_BYTES;
        const uint32_t b_st = b_rowba + s * STAGE_BYTES;

        #pragma unroll
        for (int ks = 0; ks < 4; ++ks) {
            const uint32_t a_ko = (a_kh + (uint32_t)ks * 32u) ^ a_mask;
            const uint32_t b_ko = (b_kh + (uint32_t)ks * 32u) ^ b_mask;
            uint32_t a[2][4];
            #pragma unroll
            for (int mi = 0; mi < 2; ++mi)
                LDSM_X4(a[mi][0], a[mi][1], a[mi][2], a[mi][3],
                        a_st + mi * 2048 + a_ko);
            uint32_t b[4][4];
            #pragma unroll
            for (int ni2 = 0; ni2 < 4; ++ni2)
                LDSM_X4(b[ni2][0], b[ni2][1], b[ni2][2], b[ni2][3],
                        b_st + ni2 * 2048 + b_ko);
            #pragma unroll
            for (int mi = 0; mi < 2; ++mi)
                #pragma unroll
                for (int ni = 0; ni < 8; ++ni) {
                    const int ni2 = ni >> 1;
                    const int h   = (ni & 1) * 2;   // 0 -> regs {0,1}, 1 -> {2,3}
                    MMA_16816(acc[mi][ni][0], acc[mi][ni][1], acc[mi][ni][2], acc[mi][ni][3],
                              a[mi][0], a[mi][1], a[mi][2], a[mi][3],
                              b[ni2][h], b[ni2][h + 1]);
                }
        }

        __syncthreads();   // all warps done reading stage s
        if (tid == 0 && it + STAGES < NITERS) {
            const int j = it + STAGES;
            const int seg = j >> 3, kb = j & 7;
            const int plane = seg & 1;            // segs: [x_re, x_im]
            uint32_t full = base + OFF_FULL + s * 8;
            MBARRIER_EXPECT_TX(full, STAGE_BYTES);
            uint32_t a_dst = base + OFF_STAGE0 + s * STAGE_BYTES;
            TMA_LOAD_3D(a_dst, &tmA, kb * KB, m_tile * TM, plane, full);
            TMA_LOAD_3D(a_dst + A_BYTES, &tmB, seg * 512 + kb * KB, n_tile * TN, 0, full);
        }
        if (++s == STAGES) { s = 0; ph ^= 1; }
    }

    // ---- Epilogue: fragments -> GMEM ----
    // D frag m16n8: {c0,c1} at row lane/4, cols 2*(lane%4)+{0,1}; {c2,c3} at row+8.
    const int m_base = m_tile * TM + warp_m;
    const int n_base = n_tile * TN + warp_n;
    #pragma unroll
    for (int mi = 0; mi < 2; ++mi) {
        #pragma unroll
        for (int ni = 0; ni < 8; ++ni) {
            int r0 = m_base + mi * 16 + (lane >> 2);
            int c  = n_base + ni * 8 + (lane & 3) * 2;
            int plane = c >> 9;
            int col   = c & 511;
            float* p = out + (size_t)plane * ((size_t)NROWS * OUTCH) + (size_t)r0 * OUTCH + col;
            if (r0 < NROWS)
                *reinterpret_cast<float2*>(p) = make_float2(acc[mi][ni][0], acc[mi][ni][1]);
            if (r0 + 8 < NROWS)
                *reinterpret_cast<float2*>(p + 8 * OUTCH) = make_float2(acc[mi][ni][2], acc[mi][ni][3]);
        }
    }
}

// ---------------------------------------------------------------------------
// Host launch
// ---------------------------------------------------------------------------
typedef CUresult (*EncodeTiledFn)(
    CUtensorMap*, CUtensorMapDataType, cuuint32_t, void*,
    const cuuint64_t*, const cuuint64_t*, const cuuint32_t*, const cuuint32_t*,
    CUtensorMapInterleave, CUtensorMapSwizzle, CUtensorMapL2promotion, CUtensorMapFloatOOBfill);

extern "C" void kernel_launch(void* const* d_in, const int* in_sizes, int n_in,
                              void* d_out, int out_size) {
    const float* x_re = (const float*)d_in[0];
    const float* x_im = (const float*)d_in[1];
    const float* Re   = (const float*)d_in[2];
    const float* Im   = (const float*)d_in[3];
    float* out = (float*)d_out;

    void *pA = nullptr, *pB = nullptr;
    cudaGetSymbolAddress(&pA, g_A);
    cudaGetSymbolAddress(&pB, g_B);

    const size_t P = (size_t)NROWS * INCH;
    prep_A_kernel<<<(unsigned)((P / 4 + 255) / 256), 256>>>(x_re, x_im);
    prep_B_kernel<<<(NCOLS * KTOT + 255) / 256, 256>>>(Re, Im);

    EncodeTiledFn encode = nullptr;
    cudaDriverEntryPointQueryResult qr;
    cudaGetDriverEntryPointByVersion("cuTensorMapEncodeTiled", (void**)&encode,
                                     12000, cudaEnableDefault, &qr);
    if (!encode) return;

    CUtensorMap tmA{}, tmB{};
    {
        cuuint64_t dims[3] = {INCH, NROWS, 2};
        cuuint64_t str[2]  = {INCH * 2ull, (cuuint64_t)NROWS * INCH * 2ull};
        cuuint32_t box[3]  = {KB, TM, 1};
        cuuint32_t es[3]   = {1, 1, 1};
        encode(&tmA, CU_TENSOR_MAP_DATA_TYPE_FLOAT16, 3, pA, dims, str, box, es,
               CU_TENSOR_MAP_INTERLEAVE_NONE, CU_TENSOR_MAP_SWIZZLE_128B,
               CU_TENSOR_MAP_L2_PROMOTION_L2_128B, CU_TENSOR_MAP_FLOAT_OOB_FILL_NONE);
    }
    {
        cuuint64_t dims[3] = {KTOT, NCOLS, 1};
        cuuint64_t str[2]  = {KTOT * 2ull, (cuuint64_t)NCOLS * KTOT * 2ull};
        cuuint32_t box[3]  = {KB, TN, 1};
        cuuint32_t es[3]   = {1, 1, 1};
        encode(&tmB, CU_TENSOR_MAP_DATA_TYPE_FLOAT16, 3, pB, dims, str, box, es,
               CU_TENSOR_MAP_INTERLEAVE_NONE, CU_TENSOR_MAP_SWIZZLE_128B,
               CU_TENSOR_MAP_L2_PROMOTION_L2_128B, CU_TENSOR_MAP_FLOAT_OOB_FILL_NONE);
    }

    cudaFuncSetAttribute(gemm_kernel, cudaFuncAttributeMaxDynamicSharedMemorySize, SMEM_DYN);
    dim3 grid(N_TILES, M_TILES);
    gemm_kernel<<<grid, 256, SMEM_DYN>>>(out, tmA, tmB);
}

// round 16
// speedup vs baseline: 3.1807x; 1.0615x over previous
#include <cuda_runtime.h>
#include <cuda.h>
#include <cuda_fp16.h>
#include <cstdint>

// ---------------------------------------------------------------------------
// Problem constants
// ---------------------------------------------------------------------------
#define NROWS   100000
#define INCH    512
#define OUTCH   512
#define KTOT    1024            // 2 segments * 512 : [x_re,x_im]·[W,V], all single fp16
#define NCOLS   1024            // out_re (512) ++ out_im (512)

#define TM      128             // CTA tile M
#define TN      128             // CTA tile N
#define KB      64              // fp16 elems per K-block (128 bytes = SW128 row)
#define STAGES  3               // 3 stages -> 99.3KB SMEM -> 2 CTAs/SM
#define NITERS  16              // 2 segs * (512/64)

#define M_TILES 782             // ceil(100000/128)
#define N_TILES 8               // 1024/128

// SMEM layout (relative to 1024-aligned base)
#define OFF_FULL   0            // 3 full mbarriers (8B each)
#define OFF_EMPTY  24           // 3 empty mbarriers (8B each)
#define OFF_STAGE0 1024
#define A_BYTES    (TM * KB * 2)          // 16384
#define B_BYTES    (TN * KB * 2)          // 16384
#define STAGE_BYTES (A_BYTES + B_BYTES)   // 32768
#define SMEM_DYN   (1024 /*align slack*/ + 1024 + STAGES * STAGE_BYTES)  // 100352

// ---------------------------------------------------------------------------
// Device scratch (allocation-free rule: __device__ globals)
// ---------------------------------------------------------------------------
// A planes: 0 = x_re, 1 = x_im ; each [NROWS][INCH] fp16
__device__ __half g_A[2ull * NROWS * INCH];
// B: [NCOLS][KTOT] fp16, K-major. Segments: [W, V]
//   o <  512 (out_re): W = Re,  V = -Im
//   o >= 512 (out_im): W = Im,  V =  Re
__device__ __half g_B[(size_t)NCOLS * KTOT];

// ---------------------------------------------------------------------------
// PTX helpers (generic-PTX only: no tcgen05 / TMEM / cta_group)
// ---------------------------------------------------------------------------
__device__ __forceinline__ uint32_t smem_u32(const void* p) {
    uint32_t a;
    asm("{ .reg .u64 t; cvta.to.shared.u64 t, %1; cvt.u32.u64 %0, t; }" : "=r"(a) : "l"(p));
    return a;
}
__device__ __forceinline__ uint32_t h2_as_u32(__half2 h) {
    union { __half2 h; uint32_t u; } cvt;
    cvt.h = h;
    return cvt.u;
}
#define MBARRIER_INIT(addr, cnt) \
    asm volatile("mbarrier.init.shared.b64 [%0], %1;" :: "r"((uint32_t)(addr)), "r"((uint32_t)(cnt)) : "memory")
#define MBARRIER_EXPECT_TX(addr, bytes) \
    asm volatile("mbarrier.arrive.expect_tx.shared.b64 _, [%0], %1;" :: "r"((uint32_t)(addr)), "r"((uint32_t)(bytes)) : "memory")
#define MBARRIER_ARRIVE(addr) \
    asm volatile("mbarrier.arrive.shared.b64 _, [%0];" :: "r"((uint32_t)(addr)) : "memory")
#define FENCE_PROXY_ASYNC_SHARED_CTA() \
    asm volatile("fence.proxy.async.shared::cta;" ::: "memory")

#define MBARRIER_WAIT_PARITY(mbar_smem_addr, phase_parity) do { \
    uint32_t _mbar = (uint32_t)(mbar_smem_addr); \
    uint32_t _parity = (uint32_t)(phase_parity); \
    uint32_t _done; \
    asm volatile("{\n\t.reg .pred p;\n\t" \
        "mbarrier.try_wait.parity.acquire.cta.shared::cta.b64 p, [%1], %2;\n\t" \
        "selp.b32 %0, 1, 0, p;\n\t}" : "=r"(_done) : "r"(_mbar), "r"(_parity) : "memory"); \
    if (!_done) { \
        asm volatile("{\n\t.reg .pred P1;\n\t" \
            "WAIT_LOOP_%=:\n\t" \
            "mbarrier.try_wait.parity.acquire.cta.shared::cta.b64 P1, [%0], %1, 0x989680;\n\t" \
            "@P1 bra.uni WAIT_DONE_%=;\n\t" \
            "bra.uni WAIT_LOOP_%=;\n\t" \
            "WAIT_DONE_%=:\n\t}" :: "r"(_mbar), "r"(_parity) : "memory"); \
    } \
} while(0)

#define MBARRIER_WAIT_PARITY_RELAXED(mbar_smem_addr, phase_parity) do { \
    uint32_t _mbar = (uint32_t)(mbar_smem_addr); \
    uint32_t _parity = (uint32_t)(phase_parity); \
    uint32_t _done; \
    asm volatile("{\n\t.reg .pred p;\n\t" \
        "mbarrier.try_wait.parity.relaxed.cta.shared::cta.b64 p, [%1], %2, 0x989680;\n\t" \
        "selp.b32 %0, 1, 0, p;\n\t}" : "=r"(_done) : "r"(_mbar), "r"(_parity) : "memory"); \
    if (!_done) { \
        asm volatile("{\n\t.reg .pred P1;\n\t" \
            "WAIT_LOOP_%=:\n\t" \
            "mbarrier.try_wait.parity.relaxed.cta.shared::cta.b64 P1, [%0], %1, 0x989680;\n\t" \
            "@P1 bra.uni WAIT_DONE_%=;\n\t" \
            "bra.uni WAIT_LOOP_%=;\n\t" \
            "WAIT_DONE_%=:\n\t}" :: "r"(_mbar), "r"(_parity) : "memory"); \
    } \
} while(0)

#define TMA_LOAD_3D(smem_addr, tmap, cx, cy, cz, mbar) \
    asm volatile("cp.async.bulk.tensor.3d.shared::cta.global.tile.mbarrier::complete_tx::bytes " \
        "[%0], [%1, {%2, %3, %4}], [%5];" \
        :: "r"((uint32_t)(smem_addr)), "l"(tmap), "r"((int32_t)(cx)), "r"((int32_t)(cy)), "r"((int32_t)(cz)), \
           "r"((uint32_t)(mbar)) : "memory")

#define LDSM_X4(r0, r1, r2, r3, addr) \
    asm volatile("ldmatrix.sync.aligned.m8n8.x4.shared.b16 {%0,%1,%2,%3}, [%4];" \
        : "=r"(r0), "=r"(r1), "=r"(r2), "=r"(r3) : "r"(addr))

#define MMA_16816(c0, c1, c2, c3, a0, a1, a2, a3, b0, b1) \
    asm volatile("mma.sync.aligned.m16n8k16.row.col.f32.f16.f16.f32 " \
        "{%0,%1,%2,%3}, {%4,%5,%6,%7}, {%8,%9}, {%0,%1,%2,%3};" \
        : "+f"(c0), "+f"(c1), "+f"(c2), "+f"(c3) \
        : "r"(a0), "r"(a1), "r"(a2), "r"(a3), "r"(b0), "r"(b1))

// ---------------------------------------------------------------------------
// Prep kernels
// ---------------------------------------------------------------------------
// Convert x_re / x_im to fp16 planes; vectorized: float4 in, 8B out per plane.
__global__ void prep_A_kernel(const float* __restrict__ xre, const float* __restrict__ xim) {
    const size_t P = (size_t)NROWS * INCH;                  // 51,200,000 (divisible by 4)
    size_t i4 = (size_t)blockIdx.x * blockDim.x + threadIdx.x;
    if (i4 * 4 >= P) return;
    float4 vr = reinterpret_cast<const float4*>(xre)[i4];
    float4 vi = reinterpret_cast<const float4*>(xim)[i4];
    uint2 pr = make_uint2(h2_as_u32(__floats2half2_rn(vr.x, vr.y)),
                          h2_as_u32(__floats2half2_rn(vr.z, vr.w)));
    uint2 pi = make_uint2(h2_as_u32(__floats2half2_rn(vi.x, vi.y)),
                          h2_as_u32(__floats2half2_rn(vi.z, vi.w)));
    reinterpret_cast<uint2*>(g_A)[i4] = pr;
    reinterpret_cast<uint2*>(g_A + P)[i4] = pi;
}

// Build B[1024][1024] fp16, segments [W, V]:
//   o <  512 (out_re): W = Re,  V = -Im
//   o >= 512 (out_im): W = Im,  V =  Re
__global__ void prep_B_kernel(const float* __restrict__ Re, const float* __restrict__ Im) {
    int idx = blockIdx.x * blockDim.x + threadIdx.x;
    if (idx >= NCOLS * KTOT) return;
    int o   = idx / KTOT;
    int k   = idx % KTOT;
    int seg = k >> 9;          // 0..1
    int ii  = k & 511;
    float w;
    if (o < 512) w = seg ? -Im[o * 512 + ii] : Re[o * 512 + ii];
    else         w = seg ?  Re[(o - 512) * 512 + ii] : Im[(o - 512) * 512 + ii];
    g_B[idx] = __float2half_rn(w);
}

// ---------------------------------------------------------------------------
// GEMM kernel: D[m][n] = sum_k A[m][k] * B[n][k]
// CTA tile 128x128, 8 warps (4 along M x 2 along N), warp tile 32x64.
// TMA 3-stage pipeline -> ldmatrix -> mma.sync m16n8k16 fp16, fp32 acc.
// 2 CTAs/SM. Stage recycling via arrive-counted empty mbarriers (no per-iter
// __syncthreads): warps free-run up to pipeline depth; only tid0 (producer)
// blocks on stage emptiness.
// ---------------------------------------------------------------------------
__global__ void __launch_bounds__(256, 2) gemm_kernel(
    float* __restrict__ out,
    const __grid_constant__ CUtensorMap tmA,
    const __grid_constant__ CUtensorMap tmB)
{
    extern __shared__ char smem_raw[];
    const uint32_t base = (smem_u32(smem_raw) + 1023u) & ~1023u;
    const int tid  = threadIdx.x;
    const int wid  = tid >> 5;
    const int lane = tid & 31;
    const int n_tile = blockIdx.x;   // 0..7 (fastest -> A-tile reuse in L2)
    const int m_tile = blockIdx.y;   // 0..781

    const int warp_m = (wid & 3) * 32;   // 0,32,64,96
    const int warp_n = (wid >> 2) * 64;  // 0,64

    if (tid == 0) {
        #pragma unroll
        for (int s = 0; s < STAGES; ++s) {
            MBARRIER_INIT(base + OFF_FULL + s * 8, 1);
            MBARRIER_INIT(base + OFF_EMPTY + s * 8, 256);   // all threads arrive
        }
        FENCE_PROXY_ASYNC_SHARED_CTA();
    }
    __syncthreads();

    // Prologue: fill all 3 stages (j<8 -> seg==0, plane 0).
    if (tid == 0) {
        #pragma unroll
        for (int j = 0; j < STAGES; ++j) {
            uint32_t full = base + OFF_FULL + j * 8;
            MBARRIER_EXPECT_TX(full, STAGE_BYTES);
            uint32_t a_dst = base + OFF_STAGE0 + j * STAGE_BYTES;
            TMA_LOAD_3D(a_dst, &tmA, j * KB, m_tile * TM, 0, full);
            TMA_LOAD_3D(a_dst + A_BYTES, &tmB, j * KB, n_tile * TN, 0, full);
        }
    }

    // Per-lane row bases and SW128 XOR masks (mask = (row%8)<<4, bits [6:4]).
    // k-chunk byte offset (khalf*16 + ks*32) also lives in bits [6:4], so
    // (koff ^ mask) is carry-free and must be XORed, not added.
    // A: row = warp_m + (lane&15), khalf = lane>>4
    const uint32_t a_row   = (uint32_t)(warp_m + (lane & 15));
    const uint32_t a_rowba = base + OFF_STAGE0 + a_row * 128u;
    const uint32_t a_mask  = (a_row & 7u) << 4;
    const uint32_t a_kh    = (uint32_t)(lane >> 4) * 16u;
    // B: row = warp_n + (lane&7) + (lane>>4)*8, khalf = (lane>>3)&1
    const uint32_t b_row   = (uint32_t)(warp_n + (lane & 7) + ((lane >> 4) << 3));
    const uint32_t b_rowba = base + OFF_STAGE0 + A_BYTES + b_row * 128u;
    const uint32_t b_mask  = (b_row & 7u) << 4;
    const uint32_t b_kh    = (uint32_t)((lane >> 3) & 1) * 16u;

    float acc[2][8][4];
    #pragma unroll
    for (int mi = 0; mi < 2; ++mi)
        #pragma unroll
        for (int ni = 0; ni < 8; ++ni)
            #pragma unroll
            for (int r = 0; r < 4; ++r) acc[mi][ni][r] = 0.0f;

    int s = 0, ph = 0;   // consumer (full) cursor; STAGES=3 is not a power of 2
    for (int it = 0; it < NITERS; ++it) {
        MBARRIER_WAIT_PARITY(base + OFF_FULL + s * 8, ph);

        const uint32_t a_st = a_rowba + s * STAGE_BYTES;
        const uint32_t b_st = b_rowba + s * STAGE_BYTES;

        #pragma unroll
        for (int ks = 0; ks < 4; ++ks) {
            const uint32_t a_ko = (a_kh + (uint32_t)ks * 32u) ^ a_mask;
            const uint32_t b_ko = (b_kh + (uint32_t)ks * 32u) ^ b_mask;
            uint32_t a[2][4];
            #pragma unroll
            for (int mi = 0; mi < 2; ++mi)
                LDSM_X4(a[mi][0], a[mi][1], a[mi][2], a[mi][3],
                        a_st + mi * 2048 + a_ko);
            uint32_t b[4][4];
            #pragma unroll
            for (int ni2 = 0; ni2 < 4; ++ni2)
                LDSM_X4(b[ni2][0], b[ni2][1], b[ni2][2], b[ni2][3],
                        b_st + ni2 * 2048 + b_ko);
            #pragma unroll
            for (int mi = 0; mi < 2; ++mi)
                #pragma unroll
                for (int ni = 0; ni < 8; ++ni) {
                    const int ni2 = ni >> 1;
                    const int h   = (ni & 1) * 2;   // 0 -> regs {0,1}, 1 -> {2,3}
                    MMA_16816(acc[mi][ni][0], acc[mi][ni][1], acc[mi][ni][2], acc[mi][ni][3],
                              a[mi][0], a[mi][1], a[mi][2], a[mi][3],
                              b[ni2][h], b[ni2][h + 1]);
                }
        }

        // Signal this thread is done reading stage s (non-blocking).
        MBARRIER_ARRIVE(base + OFF_EMPTY + s * 8);

        // Producer: refill stage s with chunk it+STAGES once all 256 arrived.
        if (tid == 0 && it + STAGES < NITERS) {
            MBARRIER_WAIT_PARITY_RELAXED(base + OFF_EMPTY + s * 8, ph);
            const int j = it + STAGES;
            const int seg = j >> 3, kb = j & 7;
            const int plane = seg & 1;            // segs: [x_re, x_im]
            uint32_t full = base + OFF_FULL + s * 8;
            MBARRIER_EXPECT_TX(full, STAGE_BYTES);
            uint32_t a_dst = base + OFF_STAGE0 + s * STAGE_BYTES;
            TMA_LOAD_3D(a_dst, &tmA, kb * KB, m_tile * TM, plane, full);
            TMA_LOAD_3D(a_dst + A_BYTES, &tmB, seg * 512 + kb * KB, n_tile * TN, 0, full);
        }
        if (++s == STAGES) { s = 0; ph ^= 1; }
    }

    // ---- Epilogue: fragments -> GMEM (accumulators are private; no sync) ----
    // D frag m16n8: {c0,c1} at row lane/4, cols 2*(lane%4)+{0,1}; {c2,c3} at row+8.
    const int m_base = m_tile * TM + warp_m;
    const int n_base = n_tile * TN + warp_n;
    #pragma unroll
    for (int mi = 0; mi < 2; ++mi) {
        #pragma unroll
        for (int ni = 0; ni < 8; ++ni) {
            int r0 = m_base + mi * 16 + (lane >> 2);
            int c  = n_base + ni * 8 + (lane & 3) * 2;
            int plane = c >> 9;
            int col   = c & 511;
            float* p = out + (size_t)plane * ((size_t)NROWS * OUTCH) + (size_t)r0 * OUTCH + col;
            if (r0 < NROWS)
                *reinterpret_cast<float2*>(p) = make_float2(acc[mi][ni][0], acc[mi][ni][1]);
            if (r0 + 8 < NROWS)
                *reinterpret_cast<float2*>(p + 8 * OUTCH) = make_float2(acc[mi][ni][2], acc[mi][ni][3]);
        }
    }
}

// ---------------------------------------------------------------------------
// Host launch
// ---------------------------------------------------------------------------
typedef CUresult (*EncodeTiledFn)(
    CUtensorMap*, CUtensorMapDataType, cuuint32_t, void*,
    const cuuint64_t*, const cuuint64_t*, const cuuint32_t*, const cuuint32_t*,
    CUtensorMapInterleave, CUtensorMapSwizzle, CUtensorMapL2promotion, CUtensorMapFloatOOBfill);

extern "C" void kernel_launch(void* const* d_in, const int* in_sizes, int n_in,
                              void* d_out, int out_size) {
    const float* x_re = (const float*)d_in[0];
    const float* x_im = (const float*)d_in[1];
    const float* Re   = (const float*)d_in[2];
    const float* Im   = (const float*)d_in[3];
    float* out = (float*)d_out;

    void *pA = nullptr, *pB = nullptr;
    cudaGetSymbolAddress(&pA, g_A);
    cudaGetSymbolAddress(&pB, g_B);

    const size_t P = (size_t)NROWS * INCH;
    prep_A_kernel<<<(unsigned)((P / 4 + 255) / 256), 256>>>(x_re, x_im);
    prep_B_kernel<<<(NCOLS * KTOT + 255) / 256, 256>>>(Re, Im);

    EncodeTiledFn encode = nullptr;
    cudaDriverEntryPointQueryResult qr;
    cudaGetDriverEntryPointByVersion("cuTensorMapEncodeTiled", (void**)&encode,
                                     12000, cudaEnableDefault, &qr);
    if (!encode) return;

    CUtensorMap tmA{}, tmB{};
    {
        cuuint64_t dims[3] = {INCH, NROWS, 2};
        cuuint64_t str[2]  = {INCH * 2ull, (cuuint64_t)NROWS * INCH * 2ull};
        cuuint32_t box[3]  = {KB, TM, 1};
        cuuint32_t es[3]   = {1, 1, 1};
        encode(&tmA, CU_TENSOR_MAP_DATA_TYPE_FLOAT16, 3, pA, dims, str, box, es,
               CU_TENSOR_MAP_INTERLEAVE_NONE, CU_TENSOR_MAP_SWIZZLE_128B,
               CU_TENSOR_MAP_L2_PROMOTION_L2_128B, CU_TENSOR_MAP_FLOAT_OOB_FILL_NONE);
    }
    {
        cuuint64_t dims[3] = {KTOT, NCOLS, 1};
        cuuint64_t str[2]  = {KTOT * 2ull, (cuuint64_t)NCOLS * KTOT * 2ull};
        cuuint32_t box[3]  = {KB, TN, 1};
        cuuint32_t es[3]   = {1, 1, 1};
        encode(&tmB, CU_TENSOR_MAP_DATA_TYPE_FLOAT16, 3, pB, dims, str, box, es,
               CU_TENSOR_MAP_INTERLEAVE_NONE, CU_TENSOR_MAP_SWIZZLE_128B,
               CU_TENSOR_MAP_L2_PROMOTION_L2_128B, CU_TENSOR_MAP_FLOAT_OOB_FILL_NONE);
    }

    cudaFuncSetAttribute(gemm_kernel, cudaFuncAttributeMaxDynamicSharedMemorySize, SMEM_DYN);
    dim3 grid(N_TILES, M_TILES);
    gemm_kernel<<<grid, 256, SMEM_DYN>>>(out, tmA, tmB);
}